// round 1
// baseline (speedup 1.0000x reference)
#include <cuda_runtime.h>
#include <cuda_bf16.h>
#include <math.h>

// Problem constants (fixed shapes for this problem)
#define MAXN 100000
#define MAXE 1600000
#define HDIM 128
#define GDIM 256
#define CDIM 10
#define LNUM 4
#define EPS 1e-5f

// ---------------- scratch (device globals; allocation-free) ----------------
__device__ float g_buf0[MAXN * HDIM];
__device__ float g_buf1[MAXN * HDIM];
__device__ float g_hw[MAXN * HDIM];
__device__ int   g_deg[MAXN];
__device__ float g_dinv[MAXN];
__device__ int   g_rowptr[MAXN + 1];
__device__ int   g_cursor[MAXN];
__device__ int   g_col[MAXE];
__device__ float g_wt[MAXE];
__device__ int   g_bsum[128];
__device__ int   g_boff[128];
__device__ float g_pool[GDIM * HDIM];
__device__ float g_cnt[GDIM];

// ---------------- degree count ----------------
__global__ void count_deg_kernel(const int* __restrict__ ei, int e) {
    int i = blockIdx.x * blockDim.x + threadIdx.x;
    if (i < e) atomicAdd(&g_deg[ei[e + i]], 1);   // dst = ei[E + i]
}

__global__ void dinv_kernel(int n) {
    int i = blockIdx.x * blockDim.x + threadIdx.x;
    if (i < n) g_dinv[i] = rsqrtf((float)g_deg[i] + 1.0f);
}

// ---------------- exclusive scan of g_deg -> g_rowptr ----------------
__global__ void scan1_kernel(int n) {
    __shared__ int s[1024];
    int i = blockIdx.x * 1024 + threadIdx.x;
    int v = (i < n) ? g_deg[i] : 0;
    s[threadIdx.x] = v;
    __syncthreads();
    #pragma unroll
    for (int off = 1; off < 1024; off <<= 1) {
        int t = (threadIdx.x >= off) ? s[threadIdx.x - off] : 0;
        __syncthreads();
        s[threadIdx.x] += t;
        __syncthreads();
    }
    if (i < n) g_rowptr[i] = s[threadIdx.x] - v;          // exclusive within block
    if (threadIdx.x == 1023) g_bsum[blockIdx.x] = s[1023]; // block total
}

__global__ void scan2_kernel(int nb) {
    __shared__ int s[128];
    int v = (threadIdx.x < nb) ? g_bsum[threadIdx.x] : 0;
    s[threadIdx.x] = v;
    __syncthreads();
    #pragma unroll
    for (int off = 1; off < 128; off <<= 1) {
        int t = (threadIdx.x >= off) ? s[threadIdx.x - off] : 0;
        __syncthreads();
        s[threadIdx.x] += t;
        __syncthreads();
    }
    g_boff[threadIdx.x] = s[threadIdx.x] - v;
}

__global__ void scan3_kernel(int n, int etot) {
    int i = blockIdx.x * blockDim.x + threadIdx.x;
    if (i < n) g_rowptr[i] += g_boff[i >> 10];
    if (i == 0) g_rowptr[n] = etot;
}

// ---------------- CSR fill ----------------
__global__ void fill_kernel(const int* __restrict__ ei, int e) {
    int i = blockIdx.x * blockDim.x + threadIdx.x;
    if (i >= e) return;
    int s = ei[i];
    int d = ei[e + i];
    int pos = g_rowptr[d] + atomicAdd(&g_cursor[d], 1);
    g_col[pos] = s;
    g_wt[pos] = g_dinv[s] * g_dinv[d];
}

// ---------------- GEMM: C[n,128] = A[n,128] @ B[128,128] (+bias, relu) -----
// BM=64 rows/block, 256 threads, thread tile 4 rows x 8 cols.
// fuse: 0 = none, 1 = +bias & relu
#define BM 64
#define APITCH 132
#define GEMM_SMEM ((BM * APITCH + HDIM * HDIM) * 4)

__global__ void gemm128_kernel(const float* __restrict__ A, const float* __restrict__ B,
                               const float* __restrict__ bias, float* __restrict__ C,
                               int nrows, int fuse) {
    extern __shared__ float sm[];
    float* As = sm;                    // [BM][APITCH]
    float* Bs = sm + BM * APITCH;      // [128][128]
    int tid = threadIdx.x;
    int row0 = blockIdx.x * BM;

    // load B (16384 floats = 4096 float4)
    const float4* B4 = (const float4*)B;
    float4* Bs4 = (float4*)Bs;
    #pragma unroll
    for (int i = 0; i < 16; i++) Bs4[tid + i * 256] = B4[tid + i * 256];

    // load A tile (2048 float4), guard rows
    #pragma unroll
    for (int i = 0; i < 8; i++) {
        int idx = tid + i * 256;
        int r = idx >> 5;
        int c4 = idx & 31;
        float4 v = make_float4(0.f, 0.f, 0.f, 0.f);
        if (row0 + r < nrows) v = ((const float4*)A)[(size_t)(row0 + r) * 32 + c4];
        ((float4*)(As + r * APITCH))[c4] = v;
    }
    __syncthreads();

    int cg = tid & 15;   // 16 col groups x 8 cols
    int rg = tid >> 4;   // 16 row groups x 4 rows

    float acc[4][8];
    #pragma unroll
    for (int i = 0; i < 4; i++)
        #pragma unroll
        for (int j = 0; j < 8; j++) acc[i][j] = 0.f;

    #pragma unroll 8
    for (int k = 0; k < 128; k++) {
        float a[4];
        #pragma unroll
        for (int i = 0; i < 4; i++) a[i] = As[(rg * 4 + i) * APITCH + k];
        float4 b0 = *(const float4*)(Bs + k * 128 + cg * 8);
        float4 b1 = *(const float4*)(Bs + k * 128 + cg * 8 + 4);
        #pragma unroll
        for (int i = 0; i < 4; i++) {
            acc[i][0] += a[i] * b0.x;
            acc[i][1] += a[i] * b0.y;
            acc[i][2] += a[i] * b0.z;
            acc[i][3] += a[i] * b0.w;
            acc[i][4] += a[i] * b1.x;
            acc[i][5] += a[i] * b1.y;
            acc[i][6] += a[i] * b1.z;
            acc[i][7] += a[i] * b1.w;
        }
    }

    float4 bb0 = make_float4(0.f, 0.f, 0.f, 0.f), bb1 = bb0;
    if (fuse) {
        bb0 = ((const float4*)bias)[cg * 2];
        bb1 = ((const float4*)bias)[cg * 2 + 1];
    }
    #pragma unroll
    for (int i = 0; i < 4; i++) {
        int r = row0 + rg * 4 + i;
        if (r >= nrows) continue;
        float4 o0, o1;
        o0.x = acc[i][0] + bb0.x; o0.y = acc[i][1] + bb0.y;
        o0.z = acc[i][2] + bb0.z; o0.w = acc[i][3] + bb0.w;
        o1.x = acc[i][4] + bb1.x; o1.y = acc[i][5] + bb1.y;
        o1.z = acc[i][6] + bb1.z; o1.w = acc[i][7] + bb1.w;
        if (fuse == 1) {
            o0.x = fmaxf(o0.x, 0.f); o0.y = fmaxf(o0.y, 0.f);
            o0.z = fmaxf(o0.z, 0.f); o0.w = fmaxf(o0.w, 0.f);
            o1.x = fmaxf(o1.x, 0.f); o1.y = fmaxf(o1.y, 0.f);
            o1.z = fmaxf(o1.z, 0.f); o1.w = fmaxf(o1.w, 0.f);
        }
        ((float4*)C)[(size_t)r * 32 + cg * 2]     = o0;
        ((float4*)C)[(size_t)r * 32 + cg * 2 + 1] = o1;
    }
}

// ---------------- aggregation + bias + BN + relu (one warp per node) -------
__global__ void agg_kernel(const float* __restrict__ hw, float* __restrict__ hout,
                           const float* __restrict__ bs, const float* __restrict__ gamma,
                           const float* __restrict__ beta, const float* __restrict__ rmean,
                           const float* __restrict__ rvar, int n) {
    int warp = (blockIdx.x * blockDim.x + threadIdx.x) >> 5;
    int lane = threadIdx.x & 31;
    if (warp >= n) return;
    int node = warp;
    float dv = g_dinv[node];
    float nself = dv * dv;
    const float4* hw4 = (const float4*)hw;

    float4 acc = hw4[(size_t)node * 32 + lane];
    acc.x *= nself; acc.y *= nself; acc.z *= nself; acc.w *= nself;

    int beg = g_rowptr[node];
    int end = g_rowptr[node + 1];
    for (int idx = beg; idx < end; idx++) {
        int s = g_col[idx];
        float w = g_wt[idx];
        float4 v = hw4[(size_t)s * 32 + lane];
        acc.x += w * v.x; acc.y += w * v.y;
        acc.z += w * v.z; acc.w += w * v.w;
    }

    int f = lane * 4;
    float4 b  = *(const float4*)(bs + f);
    float4 gm = *(const float4*)(gamma + f);
    float4 bt = *(const float4*)(beta + f);
    float4 rm = *(const float4*)(rmean + f);
    float4 rv = *(const float4*)(rvar + f);

    float4 o;
    o.x = fmaxf((acc.x + b.x - rm.x) * rsqrtf(rv.x + EPS) * gm.x + bt.x, 0.f);
    o.y = fmaxf((acc.y + b.y - rm.y) * rsqrtf(rv.y + EPS) * gm.y + bt.y, 0.f);
    o.z = fmaxf((acc.z + b.z - rm.z) * rsqrtf(rv.z + EPS) * gm.z + bt.z, 0.f);
    o.w = fmaxf((acc.w + b.w - rm.w) * rsqrtf(rv.w + EPS) * gm.w + bt.w, 0.f);
    ((float4*)hout)[(size_t)node * 32 + lane] = o;
}

// ---------------- global mean pool (atomics) ----------------
__global__ void pool_kernel(const float* __restrict__ h, const int* __restrict__ batch, int n) {
    int warp = (blockIdx.x * blockDim.x + threadIdx.x) >> 5;
    int lane = threadIdx.x & 31;
    if (warp >= n) return;
    int node = warp;
    int g = batch[node];
    float4 v = ((const float4*)h)[(size_t)node * 32 + lane];
    float* dst = g_pool + (size_t)g * HDIM + lane * 4;
    atomicAdd(dst + 0, v.x);
    atomicAdd(dst + 1, v.y);
    atomicAdd(dst + 2, v.z);
    atomicAdd(dst + 3, v.w);
    if (lane == 0) atomicAdd(&g_cnt[g], 1.0f);
}

// ---------------- final MLP ----------------
__global__ void mlp_kernel(const float* __restrict__ fc1w, const float* __restrict__ fc1b,
                           const float* __restrict__ fc2w, const float* __restrict__ fc2b,
                           float* __restrict__ out) {
    __shared__ float ge[HDIM];
    __shared__ float hid[64];
    int g = blockIdx.x;
    int t = threadIdx.x;  // 64 threads
    float inv = 1.0f / fmaxf(g_cnt[g], 1.0f);
    for (int i = t; i < HDIM; i += 64) ge[i] = g_pool[(size_t)g * HDIM + i] * inv;
    __syncthreads();
    float s = fc1b[t];
    #pragma unroll 8
    for (int k = 0; k < HDIM; k++) s += ge[k] * fc1w[k * 64 + t];
    hid[t] = fmaxf(s, 0.f);
    __syncthreads();
    if (t < CDIM) {
        float o = fc2b[t];
        #pragma unroll
        for (int k = 0; k < 64; k++) o += hid[k] * fc2w[k * CDIM + t];
        out[g * CDIM + t] = o;
    }
}

// ---------------- launch ----------------
extern "C" void kernel_launch(void* const* d_in, const int* in_sizes, int n_in,
                              void* d_out, int out_size) {
    if (n_in < 15) return;
    const float* x      = (const float*)d_in[0];
    const int*   ei     = (const int*)d_in[1];
    const int*   batch  = (const int*)d_in[2];
    const float* W_in   = (const float*)d_in[3];
    const float* b_in   = (const float*)d_in[4];
    const float* Ws     = (const float*)d_in[5];
    const float* bs     = (const float*)d_in[6];
    const float* gammas = (const float*)d_in[7];
    const float* betas  = (const float*)d_in[8];
    const float* rmeans = (const float*)d_in[9];
    const float* rvars  = (const float*)d_in[10];
    const float* fc1w   = (const float*)d_in[11];
    const float* fc1b   = (const float*)d_in[12];
    const float* fc2w   = (const float*)d_in[13];
    const float* fc2b   = (const float*)d_in[14];

    int n = in_sizes[0] / HDIM;      // 100000
    int e = in_sizes[1] / 2;         // 1600000
    int g = out_size / CDIM;         // 256

    void *p_buf0, *p_buf1, *p_hw, *p_deg, *p_cur, *p_pool, *p_cnt;
    cudaGetSymbolAddress(&p_buf0, g_buf0);
    cudaGetSymbolAddress(&p_buf1, g_buf1);
    cudaGetSymbolAddress(&p_hw, g_hw);
    cudaGetSymbolAddress(&p_deg, g_deg);
    cudaGetSymbolAddress(&p_cur, g_cursor);
    cudaGetSymbolAddress(&p_pool, g_pool);
    cudaGetSymbolAddress(&p_cnt, g_cnt);

    static int attr_done = 0;
    if (!attr_done) {
        cudaFuncSetAttribute(gemm128_kernel,
                             cudaFuncAttributeMaxDynamicSharedMemorySize, GEMM_SMEM);
        attr_done = 1;
    }

    // zero scratch
    cudaMemsetAsync(p_deg, 0, (size_t)n * sizeof(int));
    cudaMemsetAsync(p_cur, 0, (size_t)n * sizeof(int));
    cudaMemsetAsync(p_pool, 0, (size_t)g * HDIM * sizeof(float));
    cudaMemsetAsync(p_cnt, 0, (size_t)g * sizeof(float));

    int tpb = 256;
    int egrid = (e + tpb - 1) / tpb;
    int ngrid = (n + tpb - 1) / tpb;
    int nb = (n + 1023) / 1024;

    // graph structure
    count_deg_kernel<<<egrid, tpb>>>(ei, e);
    dinv_kernel<<<ngrid, tpb>>>(n);
    scan1_kernel<<<nb, 1024>>>(n);
    scan2_kernel<<<1, 128>>>(nb);
    scan3_kernel<<<ngrid, tpb>>>(n, e);
    fill_kernel<<<egrid, tpb>>>(ei, e);

    int ggrid = (n + BM - 1) / BM;
    int wgrid = ((size_t)n * 32 + tpb - 1) / tpb;

    float* bufA = (float*)p_buf0;
    float* bufB = (float*)p_buf1;

    // input proj: h = relu(x @ W_in + b_in)
    gemm128_kernel<<<ggrid, tpb, GEMM_SMEM>>>(x, W_in, b_in, bufA, n, 1);

    for (int l = 0; l < LNUM; l++) {
        gemm128_kernel<<<ggrid, tpb, GEMM_SMEM>>>(bufA, Ws + (size_t)l * HDIM * HDIM,
                                                  nullptr, (float*)p_hw, n, 0);
        agg_kernel<<<wgrid, tpb>>>((const float*)p_hw, bufB,
                                   bs + l * HDIM, gammas + l * HDIM, betas + l * HDIM,
                                   rmeans + l * HDIM, rvars + l * HDIM, n);
        float* t = bufA; bufA = bufB; bufB = t;
    }

    pool_kernel<<<wgrid, tpb>>>(bufA, batch, n);
    mlp_kernel<<<g, 64>>>(fc1w, fc1b, fc2w, fc2b, (float*)d_out);
}

// round 2
// speedup vs baseline: 1.0076x; 1.0076x over previous
#include <cuda_runtime.h>
#include <cuda_bf16.h>
#include <math.h>

// Problem constants (fixed shapes for this problem)
#define MAXN 100000
#define MAXE 1600000
#define HDIM 128
#define GDIM 256
#define CDIM 10
#define LNUM 4
#define EPS 1e-5f

// ---------------- scratch (device globals; allocation-free) ----------------
__device__ float g_buf0[MAXN * HDIM];
__device__ float g_buf1[MAXN * HDIM];
__device__ float g_hw[MAXN * HDIM];
__device__ int   g_deg[MAXN];
__device__ float g_dinv[MAXN];
__device__ int   g_rowptr[MAXN + 1];
__device__ int   g_cursor[MAXN];
__device__ int   g_col[MAXE];
__device__ float g_wt[MAXE];
__device__ int   g_bsum[128];
__device__ int   g_boff[128];
__device__ float g_pool[GDIM * HDIM];
__device__ float g_cnt[GDIM];

// ---------------- packed f32x2 helpers (Blackwell FFMA2) ----------------
__device__ __forceinline__ unsigned long long dup_f32x2(float a) {
    unsigned long long r;
    asm("mov.b64 %0, {%1, %1};" : "=l"(r) : "f"(a));
    return r;
}
__device__ __forceinline__ void fma_f32x2(unsigned long long& d,
                                          unsigned long long a,
                                          unsigned long long b) {
    asm("fma.rn.f32x2 %0, %1, %2, %0;" : "+l"(d) : "l"(a), "l"(b));
}
__device__ __forceinline__ float2 unpack_f32x2(unsigned long long v) {
    float2 f;
    asm("mov.b64 {%0, %1}, %2;" : "=f"(f.x), "=f"(f.y) : "l"(v));
    return f;
}

// ---------------- degree count ----------------
__global__ void count_deg_kernel(const int* __restrict__ ei, int e) {
    int i = blockIdx.x * blockDim.x + threadIdx.x;
    if (i < e) atomicAdd(&g_deg[ei[e + i]], 1);   // dst = ei[E + i]
}

__global__ void dinv_kernel(int n) {
    int i = blockIdx.x * blockDim.x + threadIdx.x;
    if (i < n) g_dinv[i] = rsqrtf((float)g_deg[i] + 1.0f);
}

// ---------------- exclusive scan of g_deg -> g_rowptr ----------------
__global__ void scan1_kernel(int n) {
    __shared__ int s[1024];
    int i = blockIdx.x * 1024 + threadIdx.x;
    int v = (i < n) ? g_deg[i] : 0;
    s[threadIdx.x] = v;
    __syncthreads();
    #pragma unroll
    for (int off = 1; off < 1024; off <<= 1) {
        int t = (threadIdx.x >= off) ? s[threadIdx.x - off] : 0;
        __syncthreads();
        s[threadIdx.x] += t;
        __syncthreads();
    }
    if (i < n) g_rowptr[i] = s[threadIdx.x] - v;          // exclusive within block
    if (threadIdx.x == 1023) g_bsum[blockIdx.x] = s[1023]; // block total
}

__global__ void scan2_kernel(int nb) {
    __shared__ int s[128];
    int v = (threadIdx.x < nb) ? g_bsum[threadIdx.x] : 0;
    s[threadIdx.x] = v;
    __syncthreads();
    #pragma unroll
    for (int off = 1; off < 128; off <<= 1) {
        int t = (threadIdx.x >= off) ? s[threadIdx.x - off] : 0;
        __syncthreads();
        s[threadIdx.x] += t;
        __syncthreads();
    }
    g_boff[threadIdx.x] = s[threadIdx.x] - v;
}

__global__ void scan3_kernel(int n, int etot) {
    int i = blockIdx.x * blockDim.x + threadIdx.x;
    if (i < n) g_rowptr[i] += g_boff[i >> 10];
    if (i == 0) g_rowptr[n] = etot;
}

// ---------------- CSR fill ----------------
__global__ void fill_kernel(const int* __restrict__ ei, int e) {
    int i = blockIdx.x * blockDim.x + threadIdx.x;
    if (i >= e) return;
    int s = ei[i];
    int d = ei[e + i];
    int pos = g_rowptr[d] + atomicAdd(&g_cursor[d], 1);
    g_col[pos] = s;
    g_wt[pos] = g_dinv[s] * g_dinv[d];
}

// ---------------- GEMM: C[n,128] = A[n,128] @ B[128,128] (+bias, relu) -----
// BM=64 rows/block, 256 threads, thread tile 4 rows x 8 cols.
// Inner loop uses packed fma.rn.f32x2 (2 fp32 FMA per FMA-pipe slot).
// fuse: 0 = none, 1 = +bias & relu
#define BM 64
#define APITCH 132
#define GEMM_SMEM ((BM * APITCH + HDIM * HDIM) * 4)

__global__ void gemm128_kernel(const float* __restrict__ A, const float* __restrict__ B,
                               const float* __restrict__ bias, float* __restrict__ C,
                               int nrows, int fuse) {
    extern __shared__ float sm[];
    float* As = sm;                    // [BM][APITCH]
    float* Bs = sm + BM * APITCH;      // [128][128]
    int tid = threadIdx.x;
    int row0 = blockIdx.x * BM;

    // load B (16384 floats = 4096 float4)
    const float4* B4 = (const float4*)B;
    float4* Bs4 = (float4*)Bs;
    #pragma unroll
    for (int i = 0; i < 16; i++) Bs4[tid + i * 256] = B4[tid + i * 256];

    // load A tile (2048 float4), guard rows
    #pragma unroll
    for (int i = 0; i < 8; i++) {
        int idx = tid + i * 256;
        int r = idx >> 5;
        int c4 = idx & 31;
        float4 v = make_float4(0.f, 0.f, 0.f, 0.f);
        if (row0 + r < nrows) v = ((const float4*)A)[(size_t)(row0 + r) * 32 + c4];
        ((float4*)(As + r * APITCH))[c4] = v;
    }
    __syncthreads();

    int cg = tid & 15;   // 16 col groups x 8 cols
    int rg = tid >> 4;   // 16 row groups x 4 rows

    // packed accumulators: 4 rows x 4 col-pairs (= 8 cols)
    unsigned long long acc[4][4];
    #pragma unroll
    for (int i = 0; i < 4; i++)
        #pragma unroll
        for (int j = 0; j < 4; j++) acc[i][j] = 0ull;

    const unsigned long long* Bs2 = (const unsigned long long*)Bs;

    #pragma unroll 8
    for (int k = 0; k < 128; k++) {
        unsigned long long ad[4];
        #pragma unroll
        for (int i = 0; i < 4; i++) ad[i] = dup_f32x2(As[(rg * 4 + i) * APITCH + k]);
        // 8 B-cols for this thread = 4 packed pairs (two 16B shared loads)
        ulonglong2 b01 = *(const ulonglong2*)(Bs2 + k * 64 + cg * 4);
        ulonglong2 b23 = *(const ulonglong2*)(Bs2 + k * 64 + cg * 4 + 2);
        #pragma unroll
        for (int i = 0; i < 4; i++) {
            fma_f32x2(acc[i][0], ad[i], b01.x);
            fma_f32x2(acc[i][1], ad[i], b01.y);
            fma_f32x2(acc[i][2], ad[i], b23.x);
            fma_f32x2(acc[i][3], ad[i], b23.y);
        }
    }

    float4 bb0 = make_float4(0.f, 0.f, 0.f, 0.f), bb1 = bb0;
    if (fuse) {
        bb0 = ((const float4*)bias)[cg * 2];
        bb1 = ((const float4*)bias)[cg * 2 + 1];
    }
    #pragma unroll
    for (int i = 0; i < 4; i++) {
        int r = row0 + rg * 4 + i;
        if (r >= nrows) continue;
        float2 p0 = unpack_f32x2(acc[i][0]);
        float2 p1 = unpack_f32x2(acc[i][1]);
        float2 p2 = unpack_f32x2(acc[i][2]);
        float2 p3 = unpack_f32x2(acc[i][3]);
        float4 o0, o1;
        o0.x = p0.x + bb0.x; o0.y = p0.y + bb0.y;
        o0.z = p1.x + bb0.z; o0.w = p1.y + bb0.w;
        o1.x = p2.x + bb1.x; o1.y = p2.y + bb1.y;
        o1.z = p3.x + bb1.z; o1.w = p3.y + bb1.w;
        if (fuse == 1) {
            o0.x = fmaxf(o0.x, 0.f); o0.y = fmaxf(o0.y, 0.f);
            o0.z = fmaxf(o0.z, 0.f); o0.w = fmaxf(o0.w, 0.f);
            o1.x = fmaxf(o1.x, 0.f); o1.y = fmaxf(o1.y, 0.f);
            o1.z = fmaxf(o1.z, 0.f); o1.w = fmaxf(o1.w, 0.f);
        }
        ((float4*)C)[(size_t)r * 32 + cg * 2]     = o0;
        ((float4*)C)[(size_t)r * 32 + cg * 2 + 1] = o1;
    }
}

// ---- aggregation + bias + BN + relu (+ optional fused mean-pool atomics) ----
__global__ void agg_kernel(const float* __restrict__ hw, float* __restrict__ hout,
                           const float* __restrict__ bs, const float* __restrict__ gamma,
                           const float* __restrict__ beta, const float* __restrict__ rmean,
                           const float* __restrict__ rvar,
                           const int* __restrict__ batch, int dopool, int n) {
    int warp = (blockIdx.x * blockDim.x + threadIdx.x) >> 5;
    int lane = threadIdx.x & 31;
    if (warp >= n) return;
    int node = warp;
    float dv = g_dinv[node];
    float nself = dv * dv;
    const float4* hw4 = (const float4*)hw;

    float4 acc = hw4[(size_t)node * 32 + lane];
    acc.x *= nself; acc.y *= nself; acc.z *= nself; acc.w *= nself;

    int beg = g_rowptr[node];
    int end = g_rowptr[node + 1];
    for (int idx = beg; idx < end; idx++) {
        int s = g_col[idx];
        float w = g_wt[idx];
        float4 v = hw4[(size_t)s * 32 + lane];
        acc.x += w * v.x; acc.y += w * v.y;
        acc.z += w * v.z; acc.w += w * v.w;
    }

    int f = lane * 4;
    float4 b  = *(const float4*)(bs + f);
    float4 gm = *(const float4*)(gamma + f);
    float4 bt = *(const float4*)(beta + f);
    float4 rm = *(const float4*)(rmean + f);
    float4 rv = *(const float4*)(rvar + f);

    float4 o;
    o.x = fmaxf((acc.x + b.x - rm.x) * rsqrtf(rv.x + EPS) * gm.x + bt.x, 0.f);
    o.y = fmaxf((acc.y + b.y - rm.y) * rsqrtf(rv.y + EPS) * gm.y + bt.y, 0.f);
    o.z = fmaxf((acc.z + b.z - rm.z) * rsqrtf(rv.z + EPS) * gm.z + bt.z, 0.f);
    o.w = fmaxf((acc.w + b.w - rm.w) * rsqrtf(rv.w + EPS) * gm.w + bt.w, 0.f);
    ((float4*)hout)[(size_t)node * 32 + lane] = o;

    if (dopool) {
        int g = batch[node];
        float* dst = g_pool + (size_t)g * HDIM + lane * 4;
        atomicAdd(dst + 0, o.x);
        atomicAdd(dst + 1, o.y);
        atomicAdd(dst + 2, o.z);
        atomicAdd(dst + 3, o.w);
        if (lane == 0) atomicAdd(&g_cnt[g], 1.0f);
    }
}

// ---------------- final MLP ----------------
__global__ void mlp_kernel(const float* __restrict__ fc1w, const float* __restrict__ fc1b,
                           const float* __restrict__ fc2w, const float* __restrict__ fc2b,
                           float* __restrict__ out) {
    __shared__ float ge[HDIM];
    __shared__ float hid[64];
    int g = blockIdx.x;
    int t = threadIdx.x;  // 64 threads
    float inv = 1.0f / fmaxf(g_cnt[g], 1.0f);
    for (int i = t; i < HDIM; i += 64) ge[i] = g_pool[(size_t)g * HDIM + i] * inv;
    __syncthreads();
    float s = fc1b[t];
    #pragma unroll 8
    for (int k = 0; k < HDIM; k++) s += ge[k] * fc1w[k * 64 + t];
    hid[t] = fmaxf(s, 0.f);
    __syncthreads();
    if (t < CDIM) {
        float o = fc2b[t];
        #pragma unroll
        for (int k = 0; k < 64; k++) o += hid[k] * fc2w[k * CDIM + t];
        out[g * CDIM + t] = o;
    }
}

// ---------------- launch ----------------
extern "C" void kernel_launch(void* const* d_in, const int* in_sizes, int n_in,
                              void* d_out, int out_size) {
    if (n_in < 15) return;
    const float* x      = (const float*)d_in[0];
    const int*   ei     = (const int*)d_in[1];
    const int*   batch  = (const int*)d_in[2];
    const float* W_in   = (const float*)d_in[3];
    const float* b_in   = (const float*)d_in[4];
    const float* Ws     = (const float*)d_in[5];
    const float* bs     = (const float*)d_in[6];
    const float* gammas = (const float*)d_in[7];
    const float* betas  = (const float*)d_in[8];
    const float* rmeans = (const float*)d_in[9];
    const float* rvars  = (const float*)d_in[10];
    const float* fc1w   = (const float*)d_in[11];
    const float* fc1b   = (const float*)d_in[12];
    const float* fc2w   = (const float*)d_in[13];
    const float* fc2b   = (const float*)d_in[14];

    int n = in_sizes[0] / HDIM;      // 100000
    int e = in_sizes[1] / 2;         // 1600000
    int g = out_size / CDIM;         // 256

    void *p_buf0, *p_buf1, *p_hw, *p_deg, *p_cur, *p_pool, *p_cnt;
    cudaGetSymbolAddress(&p_buf0, g_buf0);
    cudaGetSymbolAddress(&p_buf1, g_buf1);
    cudaGetSymbolAddress(&p_hw, g_hw);
    cudaGetSymbolAddress(&p_deg, g_deg);
    cudaGetSymbolAddress(&p_cur, g_cursor);
    cudaGetSymbolAddress(&p_pool, g_pool);
    cudaGetSymbolAddress(&p_cnt, g_cnt);

    static int attr_done = 0;
    if (!attr_done) {
        cudaFuncSetAttribute(gemm128_kernel,
                             cudaFuncAttributeMaxDynamicSharedMemorySize, GEMM_SMEM);
        attr_done = 1;
    }

    // zero scratch
    cudaMemsetAsync(p_deg, 0, (size_t)n * sizeof(int));
    cudaMemsetAsync(p_cur, 0, (size_t)n * sizeof(int));
    cudaMemsetAsync(p_pool, 0, (size_t)g * HDIM * sizeof(float));
    cudaMemsetAsync(p_cnt, 0, (size_t)g * sizeof(float));

    int tpb = 256;
    int egrid = (e + tpb - 1) / tpb;
    int ngrid = (n + tpb - 1) / tpb;
    int nb = (n + 1023) / 1024;

    // graph structure
    count_deg_kernel<<<egrid, tpb>>>(ei, e);
    dinv_kernel<<<ngrid, tpb>>>(n);
    scan1_kernel<<<nb, 1024>>>(n);
    scan2_kernel<<<1, 128>>>(nb);
    scan3_kernel<<<ngrid, tpb>>>(n, e);
    fill_kernel<<<egrid, tpb>>>(ei, e);

    int ggrid = (n + BM - 1) / BM;
    int wgrid = ((size_t)n * 32 + tpb - 1) / tpb;

    float* bufA = (float*)p_buf0;
    float* bufB = (float*)p_buf1;

    // input proj: h = relu(x @ W_in + b_in)
    gemm128_kernel<<<ggrid, tpb, GEMM_SMEM>>>(x, W_in, b_in, bufA, n, 1);

    for (int l = 0; l < LNUM; l++) {
        gemm128_kernel<<<ggrid, tpb, GEMM_SMEM>>>(bufA, Ws + (size_t)l * HDIM * HDIM,
                                                  nullptr, (float*)p_hw, n, 0);
        agg_kernel<<<wgrid, tpb>>>((const float*)p_hw, bufB,
                                   bs + l * HDIM, gammas + l * HDIM, betas + l * HDIM,
                                   rmeans + l * HDIM, rvars + l * HDIM,
                                   batch, (l == LNUM - 1) ? 1 : 0, n);
        float* t = bufA; bufA = bufB; bufB = t;
    }

    mlp_kernel<<<g, 64>>>(fc1w, fc1b, fc2w, fc2b, (float*)d_out);
}